// round 1
// baseline (speedup 1.0000x reference)
#include <cuda_runtime.h>
#include <math.h>

#define Bv 32
#define Cv 1024
#define BC_TOTAL (Bv * Cv)      // 32768
#define HW 784                  // 28*28
#define NMASK 154               // 153 masks + 1 global-max row
#define NSLOT 77                // 76 ring slots + 1 dummy
#define K1_BLK 128

// ---- static device scratch (no allocations allowed) ----
__device__ float        g_vt[NMASK * BC_TOTAL];   // vt[m][bc], ~20.2 MB
__device__ float        g_rn[NMASK * Bv];         // 1/(norm+eps) per (m,b)
__device__ unsigned int g_idx4[HW / 4];           // 4 packed u8 slot ids per float4 group
__device__ unsigned short g_axis_p[54];           // axis pixel positions (2nd quadrant pass)
__device__ unsigned char  g_axis_s[54];           // their second-quadrant slot

// ------------------------------------------------------------------
// Table init: per pixel p (i=p/28, j=p%28): dx=j-14, dy=i-14.
// rad = ceil(sqrt(dx^2+dy^2)); slot = (rad-1)*4 + quad; dummy=76 for
// center (rad 0) and corners (r2>361, covered by no mask).
// Quadrant order matches reference: (1,1),(-1,1),(1,-1),(-1,-1) with
// membership sx*dx>=0 && sy*dy>=0. Main table stores FIRST quadrant;
// axis pixels (one of dx,dy == 0, not center) get their SECOND
// quadrant via the axis table.
// ------------------------------------------------------------------
__global__ void init_tables() {
    int t = threadIdx.x;
    if (t < HW / 4) {
        unsigned int packed = 0;
        for (int k = 0; k < 4; k++) {
            int p = t * 4 + k;
            int i = p / 28, j = p % 28;
            int dx = j - 14, dy = i - 14;
            int r2 = dx * dx + dy * dy;
            unsigned int idx;
            if (r2 == 0 || r2 > 361) {
                idx = 76;  // dummy slot
            } else {
                int rad = (int)ceilf(sqrtf((float)r2));
                int q;
                if (dx >= 0 && dy >= 0)      q = 0;
                else if (dx <= 0 && dy >= 0) q = 1;
                else if (dx >= 0 && dy <= 0) q = 2;
                else                          q = 3;
                idx = (unsigned int)((rad - 1) * 4 + q);
            }
            packed |= idx << (8 * k);
        }
        g_idx4[t] = packed;
    }
    if (t >= 256 && t < 256 + 54) {
        int k = t - 256;
        int i, j;
        if (k < 27) { j = (k < 14) ? k : k + 1; i = 14; }         // row axis (dy==0)
        else { int kk = k - 27; i = (kk < 14) ? kk : kk + 1; j = 14; }  // col axis (dx==0)
        int dx = j - 14, dy = i - 14;
        int rad = abs(dx) + abs(dy);   // one of them is 0
        int q;
        if (dy == 0) q = (dx > 0) ? 2 : 3;   // first was q0/q1; second is q2/q3
        else         q = (dy > 0) ? 1 : 3;   // first was q0/q2; second is q1/q3
        g_axis_p[k] = (unsigned short)(i * 28 + j);
        g_axis_s[k] = (unsigned char)((rad - 1) * 4 + q);
    }
}

// ------------------------------------------------------------------
// k1: one thread per (b,c). Ring maxes in smem [slot][tid]: slot is
// uniform across the warp -> conflict-free. Epilogue computes per-
// quadrant prefix maxes (circle masks, seeded by the center pixel)
// and writes all 154 vt rows (coalesced over bc).
// ------------------------------------------------------------------
__global__ __launch_bounds__(K1_BLK) void k1_ringmax(const float* __restrict__ x) {
    __shared__ float sring[NSLOT * K1_BLK];
    int tid = threadIdx.x;
    int bc = blockIdx.x * K1_BLK + tid;

#pragma unroll
    for (int s = 0; s < NSLOT; s++) sring[s * K1_BLK + tid] = -INFINITY;

    const float4* __restrict__ xr = (const float4*)(x + (size_t)bc * HW);
    float gm = -INFINITY;

#pragma unroll 4
    for (int g = 0; g < HW / 4; g++) {
        float4 v = __ldg(xr + g);
        unsigned int id4 = g_idx4[g];           // uniform -> broadcast load
        int s0 = id4 & 255;
        int s1 = (id4 >> 8) & 255;
        int s2 = (id4 >> 16) & 255;
        int s3 = (id4 >> 24);
        sring[s0 * K1_BLK + tid] = fmaxf(sring[s0 * K1_BLK + tid], v.x);
        sring[s1 * K1_BLK + tid] = fmaxf(sring[s1 * K1_BLK + tid], v.y);
        sring[s2 * K1_BLK + tid] = fmaxf(sring[s2 * K1_BLK + tid], v.z);
        sring[s3 * K1_BLK + tid] = fmaxf(sring[s3 * K1_BLK + tid], v.w);
        gm = fmaxf(gm, fmaxf(fmaxf(v.x, v.y), fmaxf(v.z, v.w)));
    }

    // second-quadrant pass for the 54 axis pixels
    const float* __restrict__ xrow = x + (size_t)bc * HW;
    for (int k = 0; k < 54; k++) {
        int p = g_axis_p[k];
        int s = g_axis_s[k];
        float v = __ldg(xrow + p);
        sring[s * K1_BLK + tid] = fmaxf(sring[s * K1_BLK + tid], v);
    }

    float center = __ldg(xrow + 14 * 28 + 14);
    float* vout = g_vt + bc;
    vout[0] = fmaxf(center, 0.0f);      // mask 0: center only (zeros elsewhere)

    float c0 = center, c1 = center, c2 = center, c3 = center;
#pragma unroll
    for (int rad = 1; rad <= 19; rad++) {
        int base = (rad - 1) * 4;
        int mbase = 1 + base * 2;
        float r;
        r = sring[(base + 0) * K1_BLK + tid]; c0 = fmaxf(c0, r);
        vout[(mbase + 0) * BC_TOTAL] = fmaxf(r, 0.0f);
        vout[(mbase + 1) * BC_TOTAL] = fmaxf(c0, 0.0f);
        r = sring[(base + 1) * K1_BLK + tid]; c1 = fmaxf(c1, r);
        vout[(mbase + 2) * BC_TOTAL] = fmaxf(r, 0.0f);
        vout[(mbase + 3) * BC_TOTAL] = fmaxf(c1, 0.0f);
        r = sring[(base + 2) * K1_BLK + tid]; c2 = fmaxf(c2, r);
        vout[(mbase + 4) * BC_TOTAL] = fmaxf(r, 0.0f);
        vout[(mbase + 5) * BC_TOTAL] = fmaxf(c2, 0.0f);
        r = sring[(base + 3) * K1_BLK + tid]; c3 = fmaxf(c3, r);
        vout[(mbase + 6) * BC_TOTAL] = fmaxf(r, 0.0f);
        vout[(mbase + 7) * BC_TOTAL] = fmaxf(c3, 0.0f);
    }
    vout[153 * BC_TOTAL] = gm;          // global max, un-clamped
}

// ------------------------------------------------------------------
// k2: one block per (m,b): L2 norm over 1024 channels -> 1/(norm+eps)
// ------------------------------------------------------------------
__global__ __launch_bounds__(256) void k2_norms() {
    int blk = blockIdx.x;        // m*32 + b
    int m = blk >> 5;
    int b = blk & 31;
    int t = threadIdx.x;
    const float4* __restrict__ src = (const float4*)(g_vt + (size_t)m * BC_TOTAL + b * Cv);
    float4 v = __ldg(src + t);
    float s = v.x * v.x + v.y * v.y + v.z * v.z + v.w * v.w;
#pragma unroll
    for (int o = 16; o; o >>= 1) s += __shfl_xor_sync(0xffffffffu, s, o);
    __shared__ float ws[8];
    if ((t & 31) == 0) ws[t >> 5] = s;
    __syncthreads();
    if (t < 8) {
        float q = ws[t];
#pragma unroll
        for (int o = 4; o; o >>= 1) q += __shfl_xor_sync(0xffu, q, o);
        if (t == 0) g_rn[m * Bv + b] = 1.0f / (sqrtf(q) + 1e-6f);
    }
}

// ------------------------------------------------------------------
// k3: out[b,c] = sum_m vt[m][b,c] * rn[m][b]. Block per b (1024 ch /
// 256 threads via float4). All vt loads coalesced; rn loads uniform.
// ------------------------------------------------------------------
__global__ __launch_bounds__(256) void k3_out(float* __restrict__ out) {
    int t = threadIdx.x;
    int b = blockIdx.x;                         // 32 blocks, 1024 channels each
    const float4* __restrict__ vt = (const float4*)g_vt + (b * Cv) / 4 + t;
    const float* __restrict__ rn = g_rn + b;
    float4 acc = make_float4(0.f, 0.f, 0.f, 0.f);
#pragma unroll 2
    for (int m = 0; m < NMASK; m++) {
        float r = rn[m * Bv];
        float4 v = __ldg(vt + (size_t)m * (BC_TOTAL / 4));
        acc.x += v.x * r; acc.y += v.y * r; acc.z += v.z * r; acc.w += v.w * r;
    }
    ((float4*)out)[b * (Cv / 4) + t] = acc;
}

extern "C" void kernel_launch(void* const* d_in, const int* in_sizes, int n_in,
                              void* d_out, int out_size) {
    const float* x = (const float*)d_in[0];
    float* out = (float*)d_out;
    init_tables<<<1, 384>>>();
    k1_ringmax<<<BC_TOTAL / K1_BLK, K1_BLK>>>(x);
    k2_norms<<<NMASK * Bv, 256>>>();
    k3_out<<<Bv, 256>>>(out);
}

// round 2
// speedup vs baseline: 1.2516x; 1.2516x over previous
#include <cuda_runtime.h>
#include <math.h>

#define Bv 32
#define Cv 1024
#define BC_TOTAL (Bv * Cv)      // 32768
#define HW 784                  // 28*28
#define NMASK 154               // 153 masks + 1 global-max row
#define NSLOT 77                // 76 ring slots + 1 dummy (=76)
#define K1_T 128                // threads (= channel rows) per k1 block
#define SPITCH 68               // staging pitch in words (16B-aligned, conflict-free)
#define MSPLIT 7
#define MCHUNK 22               // 7*22 = 154

#define K1_SMEM ((NSLOT * K1_T + K1_T * SPITCH) * 4)   // 74240 bytes

// ---- static device scratch (no allocations allowed) ----
__device__ float        g_vt[NMASK * BC_TOTAL];    // vt[m][bc], ~20.2 MB
__device__ float        g_part[MSPLIT * BC_TOTAL]; // k3 partial sums
__device__ float        g_rn[NMASK * Bv];          // 1/(norm+eps) per (m,b)
__device__ unsigned int g_idx4[HW / 4];            // primary slot ids, 4 packed u8
__device__ unsigned int g_idx4b[HW / 4];           // second-quadrant slot ids (axis pixels), 76 = none

// ------------------------------------------------------------------
// Table init. Per pixel p (i=p/28, j=p%28): dx=j-14, dy=i-14.
// rad = ceil(sqrt(dx^2+dy^2)); slot = (rad-1)*4 + quad; dummy=76 for
// center (r2==0) and uncovered corners (r2>361). Quadrant order
// matches reference ((1,1),(-1,1),(1,-1),(-1,-1), membership
// sx*dx>=0 && sy*dy>=0). Primary table = first matching quadrant;
// axis pixels additionally get their second quadrant in g_idx4b.
// ------------------------------------------------------------------
__global__ void init_tables() {
    int t = threadIdx.x;
    if (t < HW / 4) {
        unsigned int pa = 0, pb = 0;
        for (int k = 0; k < 4; k++) {
            int p = t * 4 + k;
            int i = p / 28, j = p % 28;
            int dx = j - 14, dy = i - 14;
            int r2 = dx * dx + dy * dy;
            unsigned int ia = 76, ib = 76;
            if (r2 > 0 && r2 <= 361) {
                int rad = (int)ceilf(sqrtf((float)r2));
                int q;
                if (dx >= 0 && dy >= 0)      q = 0;
                else if (dx <= 0 && dy >= 0) q = 1;
                else if (dx >= 0 && dy <= 0) q = 2;
                else                          q = 3;
                ia = (unsigned int)((rad - 1) * 4 + q);
                if (dy == 0)      ib = (unsigned int)((rad - 1) * 4 + (dx > 0 ? 2 : 3));
                else if (dx == 0) ib = (unsigned int)((rad - 1) * 4 + (dy > 0 ? 1 : 3));
            }
            pa |= ia << (8 * k);
            pb |= ib << (8 * k);
        }
        g_idx4[t] = pa;
        g_idx4b[t] = pb;
    }
}

// ------------------------------------------------------------------
// k1: block handles 128 consecutive (b,c) rows. Pixels processed in
// tiles of 64: tile staged into smem with COALESCED global loads
// (consecutive lanes -> consecutive float4 within a row segment),
// then each thread scans its own row from smem (pitch 68 words ->
// conflict-free LDS.128). Ring maxes live in smem [slot][tid]
// (slot uniform across warp -> conflict-free; column private to tid
// so no syncs needed for it). Epilogue: per-quadrant prefix maxes
// (circle masks seeded by center pixel), 154 coalesced vt rows.
// ------------------------------------------------------------------
__global__ __launch_bounds__(K1_T) void k1_ringmax(const float* __restrict__ x) {
    extern __shared__ float smem[];
    float* sring = smem;                      // [NSLOT][K1_T]
    float* sx = smem + NSLOT * K1_T;          // [K1_T][SPITCH]

    int tid = threadIdx.x;
    int bc0 = blockIdx.x * K1_T;

#pragma unroll
    for (int s = 0; s < NSLOT; s++) sring[s * K1_T + tid] = -INFINITY;

    const float4* __restrict__ gsrc = (const float4*)(x + (size_t)bc0 * HW);
    float gm = -INFINITY;
    float centerv = 0.0f;

#define RMW(slot, val) { float* _a = &sring[(slot) * K1_T + tid]; *_a = fmaxf(*_a, (val)); }

    int t0 = 0;
    // 12 full tiles of 64 pixels
    for (int tile = 0; tile < 12; tile++, t0 += 64) {
        // stage: 128 rows x 16 float4
        for (int i = tid; i < K1_T * 16; i += K1_T) {
            int r = i >> 4, f = i & 15;
            float4 v = __ldg(gsrc + (size_t)r * (HW / 4) + (t0 >> 2) + f);
            *(float4*)&sx[r * SPITCH + f * 4] = v;
        }
        __syncthreads();
#pragma unroll 4
        for (int j = 0; j < 64; j += 4) {
            float4 v = *(const float4*)&sx[tid * SPITCH + j];
            int g = (t0 + j) >> 2;
            unsigned int id4 = g_idx4[g];
            RMW(id4 & 255, v.x);
            RMW((id4 >> 8) & 255, v.y);
            RMW((id4 >> 16) & 255, v.z);
            RMW(id4 >> 24, v.w);
            gm = fmaxf(gm, fmaxf(fmaxf(v.x, v.y), fmaxf(v.z, v.w)));
            unsigned int id4b = g_idx4b[g];
            if (id4b != 0x4C4C4C4Cu) {       // at least one axis pixel in group
                RMW(id4b & 255, v.x);
                RMW((id4b >> 8) & 255, v.y);
                RMW((id4b >> 16) & 255, v.z);
                RMW(id4b >> 24, v.w);
            }
            if (g == 101) centerv = v.z;     // pixel 406 = (14,14)
        }
        __syncthreads();
    }
    // remainder tile: 16 pixels (t0 = 768)
    {
        for (int i = tid; i < K1_T * 4; i += K1_T) {
            int r = i >> 2, f = i & 3;
            float4 v = __ldg(gsrc + (size_t)r * (HW / 4) + (t0 >> 2) + f);
            *(float4*)&sx[r * SPITCH + f * 4] = v;
        }
        __syncthreads();
#pragma unroll
        for (int j = 0; j < 16; j += 4) {
            float4 v = *(const float4*)&sx[tid * SPITCH + j];
            int g = (t0 + j) >> 2;
            unsigned int id4 = g_idx4[g];
            RMW(id4 & 255, v.x);
            RMW((id4 >> 8) & 255, v.y);
            RMW((id4 >> 16) & 255, v.z);
            RMW(id4 >> 24, v.w);
            gm = fmaxf(gm, fmaxf(fmaxf(v.x, v.y), fmaxf(v.z, v.w)));
            unsigned int id4b = g_idx4b[g];
            if (id4b != 0x4C4C4C4Cu) {
                RMW(id4b & 255, v.x);
                RMW((id4b >> 8) & 255, v.y);
                RMW((id4b >> 16) & 255, v.z);
                RMW(id4b >> 24, v.w);
            }
        }
    }
#undef RMW

    int bc = bc0 + tid;
    float* vout = g_vt + bc;
    vout[0] = fmaxf(centerv, 0.0f);          // mask 0: center only

    float c0 = centerv, c1 = centerv, c2 = centerv, c3 = centerv;
#pragma unroll
    for (int rad = 1; rad <= 19; rad++) {
        int base = (rad - 1) * 4;
        int mbase = 1 + base * 2;
        float r;
        r = sring[(base + 0) * K1_T + tid]; c0 = fmaxf(c0, r);
        vout[(size_t)(mbase + 0) * BC_TOTAL] = fmaxf(r, 0.0f);
        vout[(size_t)(mbase + 1) * BC_TOTAL] = fmaxf(c0, 0.0f);
        r = sring[(base + 1) * K1_T + tid]; c1 = fmaxf(c1, r);
        vout[(size_t)(mbase + 2) * BC_TOTAL] = fmaxf(r, 0.0f);
        vout[(size_t)(mbase + 3) * BC_TOTAL] = fmaxf(c1, 0.0f);
        r = sring[(base + 2) * K1_T + tid]; c2 = fmaxf(c2, r);
        vout[(size_t)(mbase + 4) * BC_TOTAL] = fmaxf(r, 0.0f);
        vout[(size_t)(mbase + 5) * BC_TOTAL] = fmaxf(c2, 0.0f);
        r = sring[(base + 3) * K1_T + tid]; c3 = fmaxf(c3, r);
        vout[(size_t)(mbase + 6) * BC_TOTAL] = fmaxf(r, 0.0f);
        vout[(size_t)(mbase + 7) * BC_TOTAL] = fmaxf(c3, 0.0f);
    }
    vout[(size_t)153 * BC_TOTAL] = gm;       // global max, un-clamped
}

// ------------------------------------------------------------------
// k2: one WARP per (m,b). 8 independent coalesced LDG.128 per lane,
// shuffle reduce, lane 0 writes 1/(norm+eps). 616 blocks x 8 warps.
// ------------------------------------------------------------------
__global__ __launch_bounds__(256) void k2_norms() {
    int warp = (blockIdx.x << 3) + (threadIdx.x >> 5);  // 0..4927 = m*32+b
    int lane = threadIdx.x & 31;
    const float4* __restrict__ src =
        (const float4*)(g_vt + (size_t)(warp >> 5) * BC_TOTAL + (warp & 31) * Cv);
    float s = 0.0f;
#pragma unroll
    for (int k = 0; k < 8; k++) {
        float4 v = __ldg(src + lane + (k << 5));
        s += v.x * v.x + v.y * v.y + v.z * v.z + v.w * v.w;
    }
#pragma unroll
    for (int o = 16; o; o >>= 1) s += __shfl_xor_sync(0xffffffffu, s, o);
    if (lane == 0) g_rn[warp] = 1.0f / (sqrtf(s) + 1e-6f);
}

// ------------------------------------------------------------------
// k3a: partial out sums. Block = (b, mask-chunk of 22). 224 blocks.
// ------------------------------------------------------------------
__global__ __launch_bounds__(256) void k3a_partial() {
    int t = threadIdx.x;
    int b = blockIdx.x & 31;
    int mc = blockIdx.x >> 5;                  // 0..6
    const float4* __restrict__ vt = (const float4*)g_vt + b * (Cv / 4) + t;
    const float* __restrict__ rn = g_rn + b;
    float4 acc = make_float4(0.f, 0.f, 0.f, 0.f);
    int m0 = mc * MCHUNK;
#pragma unroll
    for (int mm = 0; mm < MCHUNK; mm++) {
        int m = m0 + mm;
        float r = rn[m * Bv];
        float4 v = __ldg(vt + (size_t)m * (BC_TOTAL / 4));
        acc.x += v.x * r; acc.y += v.y * r; acc.z += v.z * r; acc.w += v.w * r;
    }
    ((float4*)g_part)[(size_t)mc * (BC_TOTAL / 4) + b * (Cv / 4) + t] = acc;
}

// ------------------------------------------------------------------
// k3b: reduce the 7 partials. 32 blocks x 256 threads, float4.
// ------------------------------------------------------------------
__global__ __launch_bounds__(256) void k3b_reduce(float* __restrict__ out) {
    int i = blockIdx.x * 256 + threadIdx.x;    // float4 index over 32768 floats
    float4 acc = make_float4(0.f, 0.f, 0.f, 0.f);
#pragma unroll
    for (int mc = 0; mc < MSPLIT; mc++) {
        float4 v = __ldg((const float4*)g_part + (size_t)mc * (BC_TOTAL / 4) + i);
        acc.x += v.x; acc.y += v.y; acc.z += v.z; acc.w += v.w;
    }
    ((float4*)out)[i] = acc;
}

extern "C" void kernel_launch(void* const* d_in, const int* in_sizes, int n_in,
                              void* d_out, int out_size) {
    const float* x = (const float*)d_in[0];
    float* out = (float*)d_out;
    cudaFuncSetAttribute(k1_ringmax, cudaFuncAttributeMaxDynamicSharedMemorySize, K1_SMEM);
    init_tables<<<1, 256>>>();
    k1_ringmax<<<BC_TOTAL / K1_T, K1_T, K1_SMEM>>>(x);
    k2_norms<<<NMASK * Bv / 8, 256>>>();
    k3a_partial<<<MSPLIT * Bv, 256>>>();
    k3b_reduce<<<Bv, 256>>>(out);
}

// round 3
// speedup vs baseline: 1.6911x; 1.3511x over previous
#include <cuda_runtime.h>
#include <math.h>

#define Bv 32
#define Cv 1024
#define BC_TOTAL (Bv * Cv)      // 32768
#define HW 784                  // 28*28
#define NMASK 154               // 153 masks + 1 global-max term
#define NSLOT 77                // 76 ring slots + 1 dummy (=76)
#define K1_T 64                 // threads (= channel rows) per k1 block
#define K1_BLOCKS (BC_TOTAL / K1_T)   // 512
#define TILE 32                 // pixels per staged tile
#define SPITCH 36               // staging pitch in words (conflict-free)
#define NST 78                  // state floats per (b,c): center, gm, 76 rings

// ---- static device scratch (no allocations allowed) ----
__device__ float g_st[NST * BC_TOTAL];        // compact state, ~10.2 MB
__device__ float g_sqpart[NMASK * K1_BLOCKS]; // per-block partial squared sums

// ------------------------------------------------------------------
// Compile-time slot tables. Per pixel p (i=p/28, j=p%28): dx=j-14,
// dy=i-14, r2=dx^2+dy^2. rad = ceil(sqrt(r2)); slot=(rad-1)*4+quad;
// dummy 76 for center (r2==0) and uncovered corners (r2>361).
// Quadrant order matches reference ((1,1),(-1,1),(1,-1),(-1,-1),
// membership sx*dx>=0 && sy*dy>=0). Table a = first matching
// quadrant; axis pixels additionally get a second quadrant in b.
// ------------------------------------------------------------------
struct Tabs { unsigned int a[HW / 4]; unsigned int b[HW / 4]; };
static constexpr Tabs make_tabs() {
    Tabs t = {};
    for (int g = 0; g < HW / 4; g++) {
        unsigned int pa = 0, pb = 0;
        for (int k = 0; k < 4; k++) {
            int p = g * 4 + k;
            int i = p / 28, j = p % 28;
            int dx = j - 14, dy = i - 14;
            int r2 = dx * dx + dy * dy;
            unsigned int ia = 76, ib = 76;
            if (r2 > 0 && r2 <= 361) {
                int rad = 1;
                while (rad * rad < r2) rad++;   // rad = ceil(sqrt(r2))
                int q = (dx >= 0 && dy >= 0) ? 0
                      : (dx <= 0 && dy >= 0) ? 1
                      : (dx >= 0 && dy <= 0) ? 2 : 3;
                ia = (unsigned int)((rad - 1) * 4 + q);
                if (dy == 0)      ib = (unsigned int)((rad - 1) * 4 + (dx > 0 ? 2 : 3));
                else if (dx == 0) ib = (unsigned int)((rad - 1) * 4 + (dy > 0 ? 1 : 3));
            }
            pa |= ia << (8 * k);
            pb |= ib << (8 * k);
        }
        t.a[g] = pa;
        t.b[g] = pb;
    }
    return t;
}
__constant__ Tabs c_tab = make_tabs();

// ------------------------------------------------------------------
// k1: block = 64 consecutive (b,c) rows (all same b). Pixels staged
// in 32-pixel tiles with coalesced global loads, consumed from smem
// (pitch 36: conflict-free STS.128 and LDS.128). Ring maxes in smem
// [slot][tid] (slot uniform across warp -> conflict-free; column
// private to tid). Epilogue: prefix maxes (circle masks seeded by
// center), writes 78 coalesced state floats, and reduces the 154
// squared vt values per block into g_sqpart (deterministic).
// ------------------------------------------------------------------
__global__ __launch_bounds__(K1_T) void k1_ringmax(const float* __restrict__ x) {
    __shared__ float sring[NSLOT * K1_T];     // 19712 B
    __shared__ float sx[K1_T * SPITCH];       //  9216 B

    int tid = threadIdx.x;
    int bc0 = blockIdx.x * K1_T;

#pragma unroll
    for (int s = 0; s < NSLOT; s++) sring[s * K1_T + tid] = -INFINITY;

    const float4* __restrict__ gsrc = (const float4*)(x + (size_t)bc0 * HW);
    float gm = -INFINITY;
    float centerv = 0.0f;

#define RMW(slot, val) { float* _a = &sring[(slot) * K1_T + tid]; *_a = fmaxf(*_a, (val)); }
#define PROC4(vv, gg) { \
    unsigned int _ia = c_tab.a[(gg)]; \
    RMW(_ia & 255, (vv).x); RMW((_ia >> 8) & 255, (vv).y); \
    RMW((_ia >> 16) & 255, (vv).z); RMW(_ia >> 24, (vv).w); \
    gm = fmaxf(gm, fmaxf(fmaxf((vv).x, (vv).y), fmaxf((vv).z, (vv).w))); \
    unsigned int _ib = c_tab.b[(gg)]; \
    if (_ib != 0x4C4C4C4Cu) { \
        RMW(_ib & 255, (vv).x); RMW((_ib >> 8) & 255, (vv).y); \
        RMW((_ib >> 16) & 255, (vv).z); RMW(_ib >> 24, (vv).w); \
    } \
    if ((gg) == 101) centerv = (vv).z; }

    int t0 = 0;
    // 24 full tiles of 32 pixels
    for (int tile = 0; tile < 24; tile++, t0 += TILE) {
        for (int i = tid; i < K1_T * 8; i += K1_T) {      // 8 iters
            int r = i >> 3, f = i & 7;
            float4 v = __ldg(gsrc + (size_t)r * (HW / 4) + (t0 >> 2) + f);
            *(float4*)&sx[r * SPITCH + f * 4] = v;
        }
        __syncthreads();
#pragma unroll
        for (int j = 0; j < TILE; j += 4) {
            float4 v = *(const float4*)&sx[tid * SPITCH + j];
            PROC4(v, (t0 + j) >> 2);
        }
        __syncthreads();
    }
    // remainder: 16 pixels (t0 = 768)
    {
        for (int i = tid; i < K1_T * 4; i += K1_T) {      // 4 iters
            int r = i >> 2, f = i & 3;
            float4 v = __ldg(gsrc + (size_t)r * (HW / 4) + (t0 >> 2) + f);
            *(float4*)&sx[r * SPITCH + f * 4] = v;
        }
        __syncthreads();
#pragma unroll
        for (int j = 0; j < 16; j += 4) {
            float4 v = *(const float4*)&sx[tid * SPITCH + j];
            PROC4(v, (t0 + j) >> 2);
        }
        __syncthreads();   // sx about to be reused for square partials
    }
#undef PROC4
#undef RMW

    int lane = tid & 31, wid = tid >> 5;
    float* swq = sx;                           // reuse: [NMASK][2 warps]

#define ACC(m, val) { float _s = (val) * (val); \
    _s += __shfl_xor_sync(0xffffffffu, _s, 16); \
    _s += __shfl_xor_sync(0xffffffffu, _s, 8); \
    _s += __shfl_xor_sync(0xffffffffu, _s, 4); \
    _s += __shfl_xor_sync(0xffffffffu, _s, 2); \
    _s += __shfl_xor_sync(0xffffffffu, _s, 1); \
    if (lane == 0) swq[(m) * 2 + wid] = _s; }

    float* st = g_st + bc0 + tid;
    st[0] = centerv;
    st[(size_t)1 * BC_TOTAL] = gm;
    ACC(0, fmaxf(centerv, 0.0f));
    ACC(153, gm);

    float c0 = centerv, c1 = centerv, c2 = centerv, c3 = centerv;
#pragma unroll
    for (int rad = 1; rad <= 19; rad++) {
        int base = (rad - 1) * 4;
        int mb = 1 + base * 2;
        float r;
        r = sring[(base + 0) * K1_T + tid]; c0 = fmaxf(c0, r);
        st[(size_t)(2 + base + 0) * BC_TOTAL] = r;
        ACC(mb + 0, fmaxf(r, 0.0f)); ACC(mb + 1, fmaxf(c0, 0.0f));
        r = sring[(base + 1) * K1_T + tid]; c1 = fmaxf(c1, r);
        st[(size_t)(2 + base + 1) * BC_TOTAL] = r;
        ACC(mb + 2, fmaxf(r, 0.0f)); ACC(mb + 3, fmaxf(c1, 0.0f));
        r = sring[(base + 2) * K1_T + tid]; c2 = fmaxf(c2, r);
        st[(size_t)(2 + base + 2) * BC_TOTAL] = r;
        ACC(mb + 4, fmaxf(r, 0.0f)); ACC(mb + 5, fmaxf(c2, 0.0f));
        r = sring[(base + 3) * K1_T + tid]; c3 = fmaxf(c3, r);
        st[(size_t)(2 + base + 3) * BC_TOTAL] = r;
        ACC(mb + 6, fmaxf(r, 0.0f)); ACC(mb + 7, fmaxf(c3, 0.0f));
    }
#undef ACC

    __syncthreads();
    // threads 0..153: combine the 2 warp partials -> per-block partial
    if (tid < NMASK) {
        g_sqpart[tid * K1_BLOCKS + blockIdx.x] = swq[tid * 2 + 0] + swq[tid * 2 + 1];
    }
    // note: K1_T=64 < NMASK=154, so loop the tail
    for (int m = NMASK - (NMASK % K1_T); false;) {}   // (unreachable; kept trivial)
    if (tid + K1_T < NMASK) {
        int m = tid + K1_T;
        g_sqpart[m * K1_BLOCKS + blockIdx.x] = swq[m * 2 + 0] + swq[m * 2 + 1];
    }
    if (tid + 2 * K1_T < NMASK) {
        int m = tid + 2 * K1_T;
        g_sqpart[m * K1_BLOCKS + blockIdx.x] = swq[m * 2 + 0] + swq[m * 2 + 1];
    }
}

// ------------------------------------------------------------------
// kf: 128 blocks x 256 threads. Block covers 256 bc rows of one b.
// Rebuild rn[154] from the 16 per-block partials of this b, then
// stream the 78 state floats (coalesced), replay the prefix-max
// recurrence and accumulate sum_m vt*rn -> out.
// ------------------------------------------------------------------
__global__ __launch_bounds__(256) void kf_out(float* __restrict__ out) {
    __shared__ float rn[NMASK];
    int tid = threadIdx.x;
    int b = blockIdx.x >> 2;                       // 4 blocks per b
    if (tid < NMASK) {
        const float* p = g_sqpart + tid * K1_BLOCKS + b * 16;
        float s = 0.0f;
#pragma unroll
        for (int k = 0; k < 16; k++) s += p[k];
        rn[tid] = 1.0f / (sqrtf(s) + 1e-6f);
    }
    __syncthreads();

    int bc = blockIdx.x * 256 + tid;
    const float* st = g_st + bc;
    float centerv = st[0];
    float gm = st[(size_t)1 * BC_TOTAL];
    float acc = fmaxf(centerv, 0.0f) * rn[0] + gm * rn[153];
    float c0 = centerv, c1 = centerv, c2 = centerv, c3 = centerv;
#pragma unroll
    for (int rad = 1; rad <= 19; rad++) {
        int base = (rad - 1) * 4;
        int mb = 1 + base * 2;
        float r;
        r = st[(size_t)(2 + base + 0) * BC_TOTAL]; c0 = fmaxf(c0, r);
        acc += fmaxf(r, 0.0f) * rn[mb + 0] + fmaxf(c0, 0.0f) * rn[mb + 1];
        r = st[(size_t)(2 + base + 1) * BC_TOTAL]; c1 = fmaxf(c1, r);
        acc += fmaxf(r, 0.0f) * rn[mb + 2] + fmaxf(c1, 0.0f) * rn[mb + 3];
        r = st[(size_t)(2 + base + 2) * BC_TOTAL]; c2 = fmaxf(c2, r);
        acc += fmaxf(r, 0.0f) * rn[mb + 4] + fmaxf(c2, 0.0f) * rn[mb + 5];
        r = st[(size_t)(2 + base + 3) * BC_TOTAL]; c3 = fmaxf(c3, r);
        acc += fmaxf(r, 0.0f) * rn[mb + 6] + fmaxf(c3, 0.0f) * rn[mb + 7];
    }
    out[bc] = acc;
}

extern "C" void kernel_launch(void* const* d_in, const int* in_sizes, int n_in,
                              void* d_out, int out_size) {
    const float* x = (const float*)d_in[0];
    float* out = (float*)d_out;
    k1_ringmax<<<K1_BLOCKS, K1_T>>>(x);
    kf_out<<<BC_TOTAL / 256, 256>>>(out);
}

// round 4
// speedup vs baseline: 2.0133x; 1.1905x over previous
#include <cuda_runtime.h>
#include <math.h>

#define Bv 32
#define Cv 1024
#define BC_TOTAL (Bv * Cv)      // 32768
#define HW 784                  // 28*28
#define NMASK 154               // 153 masks + 1 global-max term
#define NSLOT 77                // 76 ring slots + 1 dummy (=76)
#define K1_T 64                 // threads (= channel rows) per k1 block
#define K1_BLOCKS (BC_TOTAL / K1_T)   // 512
#define TILE 32                 // pixels per staged tile
#define SPITCH 36               // staging pitch in words (conflict-free)
#define NST 78                  // state floats per (b,c): center, gm, 76 rings

// ---- static device scratch (no allocations allowed) ----
__device__ float g_st[NST * BC_TOTAL];        // compact state, ~10.2 MB
__device__ float g_sqpart[NMASK * K1_BLOCKS]; // per-block partial squared sums

// ------------------------------------------------------------------
// Compile-time slot tables (see round 2 comment for semantics).
// ------------------------------------------------------------------
struct Tabs { unsigned int a[HW / 4]; unsigned int b[HW / 4]; };
static constexpr Tabs make_tabs() {
    Tabs t = {};
    for (int g = 0; g < HW / 4; g++) {
        unsigned int pa = 0, pb = 0;
        for (int k = 0; k < 4; k++) {
            int p = g * 4 + k;
            int i = p / 28, j = p % 28;
            int dx = j - 14, dy = i - 14;
            int r2 = dx * dx + dy * dy;
            unsigned int ia = 76, ib = 76;
            if (r2 > 0 && r2 <= 361) {
                int rad = 1;
                while (rad * rad < r2) rad++;   // rad = ceil(sqrt(r2))
                int q = (dx >= 0 && dy >= 0) ? 0
                      : (dx <= 0 && dy >= 0) ? 1
                      : (dx >= 0 && dy <= 0) ? 2 : 3;
                ia = (unsigned int)((rad - 1) * 4 + q);
                if (dy == 0)      ib = (unsigned int)((rad - 1) * 4 + (dx > 0 ? 2 : 3));
                else if (dx == 0) ib = (unsigned int)((rad - 1) * 4 + (dy > 0 ? 1 : 3));
            }
            pa |= ia << (8 * k);
            pb |= ib << (8 * k);
        }
        t.a[g] = pa;
        t.b[g] = pb;
    }
    return t;
}
__constant__ Tabs c_tab = make_tabs();

// ------------------------------------------------------------------
// k1: block = 64 consecutive (b,c) rows. SOFTWARE-PIPELINED tiles:
// prefetch tile t+1 into registers while consuming tile t from smem,
// so DRAM latency overlaps the LDS/RMW work. Ring maxes in smem
// [slot][tid] (slot uniform across warp -> conflict-free). Epilogue:
// prefix maxes, 78 coalesced state floats, inline squared-norm
// partials per block (deterministic, no atomics).
// ------------------------------------------------------------------
__global__ __launch_bounds__(K1_T) void k1_ringmax(const float* __restrict__ x) {
    __shared__ float sring[NSLOT * K1_T];     // 19712 B
    __shared__ float sx[K1_T * SPITCH];       //  9216 B

    int tid = threadIdx.x;
    int bc0 = blockIdx.x * K1_T;

#pragma unroll
    for (int s = 0; s < NSLOT; s++) sring[s * K1_T + tid] = -INFINITY;

    const float4* __restrict__ gsrc = (const float4*)(x + (size_t)bc0 * HW);
    float gm = -INFINITY;
    float centerv = 0.0f;

#define RMW(slot, val) { float* _a = &sring[(slot) * K1_T + tid]; *_a = fmaxf(*_a, (val)); }
#define PROC4(vv, gg) { \
    unsigned int _ia = c_tab.a[(gg)]; \
    RMW(_ia & 255, (vv).x); RMW((_ia >> 8) & 255, (vv).y); \
    RMW((_ia >> 16) & 255, (vv).z); RMW(_ia >> 24, (vv).w); \
    gm = fmaxf(gm, fmaxf(fmaxf((vv).x, (vv).y), fmaxf((vv).z, (vv).w))); \
    unsigned int _ib = c_tab.b[(gg)]; \
    if (_ib != 0x4C4C4C4Cu) { \
        RMW(_ib & 255, (vv).x); RMW((_ib >> 8) & 255, (vv).y); \
        RMW((_ib >> 16) & 255, (vv).z); RMW(_ib >> 24, (vv).w); \
    } \
    if ((gg) == 101) centerv = (vv).z; }

    // Prefetch mappings:
    //  full tile (32 px, 8 f4/row): thread covers rows (tid>>3)+8f, col (tid&7)
    //  rem  tile (16 px, 4 f4/row): thread covers rows (tid>>2)+16f, col (tid&3)
    float4 rr[8];
    {   // prefetch tile 0
        int rb = tid >> 3, cq = tid & 7;
#pragma unroll
        for (int f = 0; f < 8; f++)
            rr[f] = __ldg(gsrc + (size_t)(rb + 8 * f) * (HW / 4) + cq);
    }

    for (int tile = 0; tile < 25; tile++) {
        int t0 = tile * TILE;
        bool full = (tile < 24);
        __syncthreads();                      // (A) prior consume done
        if (full) {
            int rb = tid >> 3, cq = tid & 7;
#pragma unroll
            for (int f = 0; f < 8; f++)
                *(float4*)&sx[(rb + 8 * f) * SPITCH + cq * 4] = rr[f];
        } else {
            int rb = tid >> 2, cq = tid & 3;
#pragma unroll
            for (int f = 0; f < 4; f++)
                *(float4*)&sx[(rb + 16 * f) * SPITCH + cq * 4] = rr[f];
        }
        __syncthreads();                      // (B) sx staged
        // prefetch next tile (overlaps with consume below)
        if (tile + 1 < 24) {
            int rb = tid >> 3, cq = tid & 7;
            int q0 = (tile + 1) * (TILE / 4);
#pragma unroll
            for (int f = 0; f < 8; f++)
                rr[f] = __ldg(gsrc + (size_t)(rb + 8 * f) * (HW / 4) + q0 + cq);
        } else if (tile + 1 == 24) {
            int rb = tid >> 2, cq = tid & 3;
            int q0 = 24 * (TILE / 4);
#pragma unroll
            for (int f = 0; f < 4; f++)
                rr[f] = __ldg(gsrc + (size_t)(rb + 16 * f) * (HW / 4) + q0 + cq);
        }
        // consume current tile
        if (full) {
#pragma unroll
            for (int j = 0; j < TILE; j += 4) {
                float4 v = *(const float4*)&sx[tid * SPITCH + j];
                PROC4(v, (t0 + j) >> 2);
            }
        } else {
#pragma unroll
            for (int j = 0; j < 16; j += 4) {
                float4 v = *(const float4*)&sx[tid * SPITCH + j];
                PROC4(v, (t0 + j) >> 2);
            }
        }
    }
    __syncthreads();                          // sx about to be reused
#undef PROC4
#undef RMW

    int lane = tid & 31, wid = tid >> 5;
    float* swq = sx;                           // reuse: [NMASK][2 warps]

#define ACC(m, val) { float _s = (val) * (val); \
    _s += __shfl_xor_sync(0xffffffffu, _s, 16); \
    _s += __shfl_xor_sync(0xffffffffu, _s, 8); \
    _s += __shfl_xor_sync(0xffffffffu, _s, 4); \
    _s += __shfl_xor_sync(0xffffffffu, _s, 2); \
    _s += __shfl_xor_sync(0xffffffffu, _s, 1); \
    if (lane == 0) swq[(m) * 2 + wid] = _s; }

    float* st = g_st + bc0 + tid;
    st[0] = centerv;
    st[(size_t)1 * BC_TOTAL] = gm;
    ACC(0, fmaxf(centerv, 0.0f));
    ACC(153, gm);

    float c0 = centerv, c1 = centerv, c2 = centerv, c3 = centerv;
#pragma unroll
    for (int rad = 1; rad <= 19; rad++) {
        int base = (rad - 1) * 4;
        int mb = 1 + base * 2;
        float r;
        r = sring[(base + 0) * K1_T + tid]; c0 = fmaxf(c0, r);
        st[(size_t)(2 + base + 0) * BC_TOTAL] = r;
        ACC(mb + 0, fmaxf(r, 0.0f)); ACC(mb + 1, fmaxf(c0, 0.0f));
        r = sring[(base + 1) * K1_T + tid]; c1 = fmaxf(c1, r);
        st[(size_t)(2 + base + 1) * BC_TOTAL] = r;
        ACC(mb + 2, fmaxf(r, 0.0f)); ACC(mb + 3, fmaxf(c1, 0.0f));
        r = sring[(base + 2) * K1_T + tid]; c2 = fmaxf(c2, r);
        st[(size_t)(2 + base + 2) * BC_TOTAL] = r;
        ACC(mb + 4, fmaxf(r, 0.0f)); ACC(mb + 5, fmaxf(c2, 0.0f));
        r = sring[(base + 3) * K1_T + tid]; c3 = fmaxf(c3, r);
        st[(size_t)(2 + base + 3) * BC_TOTAL] = r;
        ACC(mb + 6, fmaxf(r, 0.0f)); ACC(mb + 7, fmaxf(c3, 0.0f));
    }
#undef ACC

    __syncthreads();
    if (tid < NMASK)
        g_sqpart[tid * K1_BLOCKS + blockIdx.x] = swq[tid * 2 + 0] + swq[tid * 2 + 1];
    if (tid + K1_T < NMASK) {
        int m = tid + K1_T;
        g_sqpart[m * K1_BLOCKS + blockIdx.x] = swq[m * 2 + 0] + swq[m * 2 + 1];
    }
    if (tid + 2 * K1_T < NMASK) {
        int m = tid + 2 * K1_T;
        g_sqpart[m * K1_BLOCKS + blockIdx.x] = swq[m * 2 + 0] + swq[m * 2 + 1];
    }
}

// ------------------------------------------------------------------
// kf: block = 256 threads = 4 sub-groups x 64 bc rows. Sub s handles
// a radius range, recomputing the prefix maxes up to its range start
// (extra reads, but 4x thread parallelism). Fully unrolled chunks.
// ------------------------------------------------------------------
template<int LO, int HI>
__device__ __forceinline__ float chunk_acc(const float* __restrict__ st,
                                           const float* __restrict__ rn,
                                           float centerv) {
    float c0 = centerv, c1 = centerv, c2 = centerv, c3 = centerv;
    float acc = 0.0f;
#pragma unroll
    for (int rad = 1; rad <= HI; rad++) {
        int base = (rad - 1) * 4;
        int mb = 1 + base * 2;
        float r0 = st[(size_t)(2 + base + 0) * BC_TOTAL]; c0 = fmaxf(c0, r0);
        float r1 = st[(size_t)(2 + base + 1) * BC_TOTAL]; c1 = fmaxf(c1, r1);
        float r2 = st[(size_t)(2 + base + 2) * BC_TOTAL]; c2 = fmaxf(c2, r2);
        float r3 = st[(size_t)(2 + base + 3) * BC_TOTAL]; c3 = fmaxf(c3, r3);
        if (rad >= LO) {
            acc += fmaxf(r0, 0.0f) * rn[mb + 0] + fmaxf(c0, 0.0f) * rn[mb + 1];
            acc += fmaxf(r1, 0.0f) * rn[mb + 2] + fmaxf(c1, 0.0f) * rn[mb + 3];
            acc += fmaxf(r2, 0.0f) * rn[mb + 4] + fmaxf(c2, 0.0f) * rn[mb + 5];
            acc += fmaxf(r3, 0.0f) * rn[mb + 6] + fmaxf(c3, 0.0f) * rn[mb + 7];
        }
    }
    return acc;
}

__global__ __launch_bounds__(256) void kf_out(float* __restrict__ out) {
    __shared__ float rn[NMASK];
    __shared__ float part[4 * 64];
    int tid = threadIdx.x;
    int blk = blockIdx.x;                      // 512 blocks, 64 bc each
    int b = blk >> 4;                          // 16 blocks per batch b
    if (tid < NMASK) {
        const float* p = g_sqpart + tid * K1_BLOCKS + b * 16;
        float s = 0.0f;
#pragma unroll
        for (int k = 0; k < 16; k++) s += p[k];
        rn[tid] = 1.0f / (sqrtf(s) + 1e-6f);
    }
    __syncthreads();

    int sub = tid >> 6;
    int t = tid & 63;
    int bc = blk * 64 + t;
    const float* st = g_st + bc;
    float centerv = __ldg(st);
    float acc;
    if (sub == 0) {
        acc = chunk_acc<1, 5>(st, rn, centerv)
            + fmaxf(centerv, 0.0f) * rn[0]
            + __ldg(st + (size_t)BC_TOTAL) * rn[153];   // gm row
    } else if (sub == 1) {
        acc = chunk_acc<6, 10>(st, rn, centerv);
    } else if (sub == 2) {
        acc = chunk_acc<11, 15>(st, rn, centerv);
    } else {
        acc = chunk_acc<16, 19>(st, rn, centerv);
    }
    part[sub * 64 + t] = acc;
    __syncthreads();
    if (tid < 64) {
        out[blk * 64 + tid] = part[tid] + part[64 + tid] + part[128 + tid] + part[192 + tid];
    }
}

extern "C" void kernel_launch(void* const* d_in, const int* in_sizes, int n_in,
                              void* d_out, int out_size) {
    const float* x = (const float*)d_in[0];
    float* out = (float*)d_out;
    k1_ringmax<<<K1_BLOCKS, K1_T>>>(x);
    kf_out<<<K1_BLOCKS, 256>>>(out);
}

// round 6
// speedup vs baseline: 3.6370x; 1.8065x over previous
#include <cuda_runtime.h>
#include <math.h>

#define Bv 32
#define Cv 1024
#define BC_TOTAL (Bv * Cv)      // 32768
#define HW 784                  // 28*28
#define NMASK 154               // 153 masks + 1 global-max term
#define K1_BLOCKS 512           // 64 channels per block
#define SXPITCH 113             // words per channel row in staging (odd -> conflict-free)
#define NST 78                  // state floats per (b,c): center, gm, 76 rings

// ---- static device scratch (no allocations allowed) ----
__device__ float g_st[NST * BC_TOTAL];        // compact state, ~10.2 MB
__device__ float g_sqpart[NMASK * K1_BLOCKS]; // per-block partial squared sums

// ------------------------------------------------------------------
// Compile-time per-(quadrant, tile) pixel lists.
// Tile t stages rows {2t, 2t+1} (chunk 0) and {26-2t, 27-2t} (chunk 1),
// 112 pixels, stored transposed-in-chunk: pixel pp -> word
// chunk*56 + (pp%4)*14 + pp/4 (float4 staging is STS.32-friendly,
// consume reads a uniform word index per warp -> conflict-free).
// Entry = word | (rad<<8); rad: 1..19 ring, 0 = gm-only corner,
// 31 = center (q0 only).
// Quadrants (ref order): q0 (dx>=0,dy>=0) q1 (dx<=0,dy>=0)
//                        q2 (dx>=0,dy<=0) q3 (dx<=0,dy<=0)
// ------------------------------------------------------------------
struct QLists { unsigned short e[4][7][48]; int cnt[4][7]; };
static constexpr QLists make_lists() {
    QLists L = {};
    for (int q = 0; q < 4; q++) for (int t = 0; t < 7; t++) L.cnt[q][t] = 0;
    for (int i = 0; i < 28; i++) for (int j = 0; j < 28; j++) {
        int dx = j - 14, dy = i - 14;
        int r2 = dx * dx + dy * dy;
        int t = 0, lp = 0;
        if (i < 14) { t = i / 2; lp = (i & 1) * 28 + j; }
        else { t = (27 - i) / 2; lp = 56 + (i - (26 - 2 * ((27 - i) / 2))) * 28 + j; }
        int pp = lp % 56, chunk = lp / 56;
        int word = chunk * 56 + (pp % 4) * 14 + (pp / 4);
        int rad = 0;
        if (r2 == 0) rad = 31;
        else if (r2 <= 361) { rad = 1; while (rad * rad < r2) rad++; }
        else rad = 0;   // corner: contributes to global max only
        bool inq[4] = { dx >= 0 && dy >= 0, dx <= 0 && dy >= 0,
                        dx >= 0 && dy <= 0, dx <= 0 && dy <= 0 };
        for (int q = 0; q < 4; q++) {
            if (rad == 31) { if (q != 0) continue; }
            else if (!inq[q]) continue;
            L.e[q][t][L.cnt[q][t]++] = (unsigned short)(word | (rad << 8));
        }
    }
    return L;
}
static constexpr QLists LISTS = make_lists();

// ------------------------------------------------------------------
// Fully unrolled consume steps: all offsets / rad indices fold to
// immediates; ring accumulators r[19] stay in registers.
// ------------------------------------------------------------------
template<int Q, int T, int K, int N>
struct Steps {
    __device__ __forceinline__ static void run(const float* sxc, float* r,
                                               float& gm0, float& cen) {
        constexpr unsigned e = LISTS.e[Q][T][K];
        constexpr int rad = e >> 8;
        float v = sxc[e & 255];
        if constexpr (rad == 31) { cen = v; }
        else if constexpr (rad == 0) { gm0 = fmaxf(gm0, v); }
        else { r[rad - 1] = fmaxf(r[rad - 1], v); }
        Steps<Q, T, K + 1, N>::run(sxc, r, gm0, cen);
    }
};
template<int Q, int T, int N>
struct Steps<Q, T, N, N> {
    __device__ __forceinline__ static void run(const float*, float*, float&, float&) {}
};

// Stage tile T: two 2-row chunks, 896 float4 each, coalesced LDG.128,
// transposed STS.32 into sx[ch*SXPITCH + chunk*56 + k*14 + f].
template<int T>
__device__ __forceinline__ void stage_tile(const float4* __restrict__ gsrc,
                                           float* sx, int tid) {
#pragma unroll
    for (int c2 = 0; c2 < 2; c2++) {
        const int base = (c2 == 0) ? (14 * T) : ((26 - 2 * T) * 7);
        const int w0c = c2 * 56;
#pragma unroll
        for (int it = 0; it < 4; it++) {
            int m = tid + it * 256;
            if (it < 3 || tid < 128) {
                int ch = m / 14, f = m % 14;
                float4 v = __ldg(gsrc + (size_t)ch * (HW / 4) + base + f);
                float* w = sx + ch * SXPITCH + w0c + f;
                w[0] = v.x; w[14] = v.y; w[28] = v.z; w[42] = v.w;
            }
        }
    }
}

template<int T>
__device__ __forceinline__ void consume_dispatch(int q, const float* sxc, float* r,
                                                 float& gm0, float& cen) {
    if (q == 0)      Steps<0, T, 0, LISTS.cnt[0][T]>::run(sxc, r, gm0, cen);
    else if (q == 1) Steps<1, T, 0, LISTS.cnt[1][T]>::run(sxc, r, gm0, cen);
    else if (q == 2) Steps<2, T, 0, LISTS.cnt[2][T]>::run(sxc, r, gm0, cen);
    else             Steps<3, T, 0, LISTS.cnt[3][T]>::run(sxc, r, gm0, cen);
}

template<int T>
__device__ __forceinline__ void tiles(const float4* __restrict__ gsrc, float* sx,
                                      int tid, int q, const float* sxc, float* r,
                                      float& gm0, float& cen) {
    stage_tile<T>(gsrc, sx, tid);
    __syncthreads();
    consume_dispatch<T>(q, sxc, r, gm0, cen);   // no syncs inside (warp-uniform q)
    __syncthreads();
    if constexpr (T < 6) tiles<T + 1>(gsrc, sx, tid, q, sxc, r, gm0, cen);
}

// ------------------------------------------------------------------
// k1: block = 64 channels x 4 quadrant-threads (256). Ring maxes in
// registers. Epilogue: broadcast center, combine quadrant gm, prefix
// maxes (circle masks), coalesced state writes, inline squared-norm
// warp reductions -> g_sqpart (deterministic, no atomics).
// ------------------------------------------------------------------
__global__ __launch_bounds__(256) void k1_ringmax(const float* __restrict__ x) {
    __shared__ float sx[64 * SXPITCH];         // 28928 B
    int tid = threadIdx.x;
    int q = tid >> 6;
    int ch = tid & 63;
    int lane = tid & 31;
    int half = (tid >> 5) & 1;
    int bc0 = blockIdx.x * 64;

    const float4* gsrc = (const float4*)(x + (size_t)bc0 * HW);
    float r[19];
#pragma unroll
    for (int i = 0; i < 19; i++) r[i] = -INFINITY;
    float gm0 = -INFINITY, cen = 0.0f;

    tiles<0>(gsrc, sx, tid, q, sx + ch * SXPITCH, r, gm0, cen);

    // ---- epilogue (sx reused; last tiles<> ended with __syncthreads) ----
    float* scen = sx;                 // [64]
    float* sgm = sx + 64;             // [4][64]
    float* spart = sx + 64 + 256;     // [NMASK][2]

    if (q == 0) scen[ch] = cen;
    __syncthreads();
    float centerv = scen[ch];

    // quadrant gm = max(rings, corners, center)
    float gmq = fmaxf(gm0, centerv);
#pragma unroll
    for (int i = 0; i < 19; i++) gmq = fmaxf(gmq, r[i]);
    sgm[q * 64 + ch] = gmq;
    __syncthreads();

#define WRED(m, val) { float _s = (val) * (val); \
    _s += __shfl_xor_sync(0xffffffffu, _s, 16); \
    _s += __shfl_xor_sync(0xffffffffu, _s, 8); \
    _s += __shfl_xor_sync(0xffffffffu, _s, 4); \
    _s += __shfl_xor_sync(0xffffffffu, _s, 2); \
    _s += __shfl_xor_sync(0xffffffffu, _s, 1); \
    if (lane == 0) spart[(m) * 2 + half] = _s; }

    float* st = g_st + bc0 + ch;
    if (q == 0) {
        float gmf = fmaxf(fmaxf(sgm[ch], sgm[64 + ch]),
                          fmaxf(sgm[128 + ch], sgm[192 + ch]));
        st[0] = centerv;
        st[(size_t)BC_TOTAL] = gmf;
        WRED(0, fmaxf(centerv, 0.0f));
        WRED(153, gmf);
    }

    float c = centerv;
#pragma unroll
    for (int rad = 1; rad <= 19; rad++) {
        float rv = r[rad - 1];
        c = fmaxf(c, rv);
        st[(size_t)(2 + (rad - 1) * 4 + q) * BC_TOTAL] = rv;
        int mb = 1 + (rad - 1) * 8 + q * 2;
        WRED(mb, fmaxf(rv, 0.0f));
        WRED(mb + 1, fmaxf(c, 0.0f));
    }
#undef WRED

    __syncthreads();
    if (tid < NMASK)
        g_sqpart[tid * K1_BLOCKS + blockIdx.x] = spart[tid * 2] + spart[tid * 2 + 1];
}

// ------------------------------------------------------------------
// kf: unchanged (13 us). Block = 4 sub-groups x 64 bc; sub s handles
// a radius range, recomputing prefix up to its range start.
// ------------------------------------------------------------------
template<int LO, int HI>
__device__ __forceinline__ float chunk_acc(const float* __restrict__ st,
                                           const float* __restrict__ rn,
                                           float centerv) {
    float c0 = centerv, c1 = centerv, c2 = centerv, c3 = centerv;
    float acc = 0.0f;
#pragma unroll
    for (int rad = 1; rad <= HI; rad++) {
        int base = (rad - 1) * 4;
        int mb = 1 + base * 2;
        float r0 = st[(size_t)(2 + base + 0) * BC_TOTAL]; c0 = fmaxf(c0, r0);
        float r1 = st[(size_t)(2 + base + 1) * BC_TOTAL]; c1 = fmaxf(c1, r1);
        float r2 = st[(size_t)(2 + base + 2) * BC_TOTAL]; c2 = fmaxf(c2, r2);
        float r3 = st[(size_t)(2 + base + 3) * BC_TOTAL]; c3 = fmaxf(c3, r3);
        if (rad >= LO) {
            acc += fmaxf(r0, 0.0f) * rn[mb + 0] + fmaxf(c0, 0.0f) * rn[mb + 1];
            acc += fmaxf(r1, 0.0f) * rn[mb + 2] + fmaxf(c1, 0.0f) * rn[mb + 3];
            acc += fmaxf(r2, 0.0f) * rn[mb + 4] + fmaxf(c2, 0.0f) * rn[mb + 5];
            acc += fmaxf(r3, 0.0f) * rn[mb + 6] + fmaxf(c3, 0.0f) * rn[mb + 7];
        }
    }
    return acc;
}

__global__ __launch_bounds__(256) void kf_out(float* __restrict__ out) {
    __shared__ float rn[NMASK];
    __shared__ float part[4 * 64];
    int tid = threadIdx.x;
    int blk = blockIdx.x;                      // 512 blocks, 64 bc each
    int b = blk >> 4;                          // 16 k1-blocks per batch b
    if (tid < NMASK) {
        const float* p = g_sqpart + tid * K1_BLOCKS + b * 16;
        float s = 0.0f;
#pragma unroll
        for (int k = 0; k < 16; k++) s += p[k];
        rn[tid] = 1.0f / (sqrtf(s) + 1e-6f);
    }
    __syncthreads();

    int sub = tid >> 6;
    int t = tid & 63;
    int bc = blk * 64 + t;
    const float* st = g_st + bc;
    float centerv = __ldg(st);
    float acc;
    if (sub == 0) {
        acc = chunk_acc<1, 5>(st, rn, centerv)
            + fmaxf(centerv, 0.0f) * rn[0]
            + __ldg(st + (size_t)BC_TOTAL) * rn[153];
    } else if (sub == 1) {
        acc = chunk_acc<6, 10>(st, rn, centerv);
    } else if (sub == 2) {
        acc = chunk_acc<11, 15>(st, rn, centerv);
    } else {
        acc = chunk_acc<16, 19>(st, rn, centerv);
    }
    part[sub * 64 + t] = acc;
    __syncthreads();
    if (tid < 64) {
        out[blk * 64 + tid] = part[tid] + part[64 + tid] + part[128 + tid] + part[192 + tid];
    }
}

extern "C" void kernel_launch(void* const* d_in, const int* in_sizes, int n_in,
                              void* d_out, int out_size) {
    const float* x = (const float*)d_in[0];
    float* out = (float*)d_out;
    k1_ringmax<<<K1_BLOCKS, 256>>>(x);
    kf_out<<<K1_BLOCKS, 256>>>(out);
}